// round 12
// baseline (speedup 1.0000x reference)
#include <cuda_runtime.h>
#include <cuda_fp16.h>
#include <cstdint>
#include <math.h>

#define Tn 4096
#define Hn 1024
#define In 2816
#define En 7

// ---------------- static scratch ----------------
__device__ __half xh_buf[(size_t)Tn * Hn];
__device__ __half wgs_h[(size_t)In * Hn];
__device__ __half wus_h[(size_t)In * Hn];
__device__ __half wds_h[(size_t)Hn * In];
__device__ __half wg_h[(size_t)En * In * Hn];
__device__ __half wu_h[(size_t)En * In * Hn];
__device__ __half wd_h[(size_t)En * Hn * In];
__device__ __half h_buf[(size_t)Tn * In];
__device__ __half h2_buf[(size_t)2 * Tn * In];
__device__ float  dummy_logits[(size_t)Tn * En];

__device__ int   d_counts[En];
__device__ int   d_offsets[En];
__device__ int   d_cursor[En];
__device__ int   d_sel[Tn * 2];
__device__ float d_wgt[Tn * 2];
__device__ int   d_slot_token[2 * Tn];
__device__ float d_slot_wgt[2 * Tn];

// ---------------- streams/events (created at load time; not device-memory
// allocations) ----------------
struct SideStream {
    cudaStream_t s2, s3;
    cudaEvent_t  evFork, evXh, evRoute, evDh, evOut, evDone;
    SideStream() {
        cudaStreamCreateWithFlags(&s2, cudaStreamNonBlocking);
        cudaStreamCreateWithFlags(&s3, cudaStreamNonBlocking);
        cudaEventCreateWithFlags(&evFork,  cudaEventDisableTiming);
        cudaEventCreateWithFlags(&evXh,    cudaEventDisableTiming);
        cudaEventCreateWithFlags(&evRoute, cudaEventDisableTiming);
        cudaEventCreateWithFlags(&evDh,    cudaEventDisableTiming);
        cudaEventCreateWithFlags(&evOut,   cudaEventDisableTiming);
        cudaEventCreateWithFlags(&evDone,  cudaEventDisableTiming);
    }
};
static SideStream g_ss;

// ---------------- PTX helpers (portable, sm_80+) ----------------
__device__ __forceinline__ uint32_t smem_u32(const void* p) {
    uint32_t a;
    asm("{ .reg .u64 t; cvta.to.shared.u64 t, %1; cvt.u32.u64 %0, t; }" : "=r"(a) : "l"(p));
    return a;
}
__device__ __forceinline__ void cpasync16(uint32_t dst, const void* src) {
    asm volatile("cp.async.cg.shared.global [%0], [%1], 16;" :: "r"(dst), "l"(src) : "memory");
}
__device__ __forceinline__ void cpcommit() {
    asm volatile("cp.async.commit_group;" ::: "memory");
}
__device__ __forceinline__ void cpwait(int n) {
    if (n <= 0)      asm volatile("cp.async.wait_group 0;" ::: "memory");
    else if (n == 1) asm volatile("cp.async.wait_group 1;" ::: "memory");
    else             asm volatile("cp.async.wait_group 2;" ::: "memory");
}
__device__ __forceinline__ void ldsm_x4(uint32_t* r, uint32_t addr) {
    asm volatile("ldmatrix.sync.aligned.m8n8.x4.shared.b16 {%0,%1,%2,%3}, [%4];"
        : "=r"(r[0]), "=r"(r[1]), "=r"(r[2]), "=r"(r[3]) : "r"(addr));
}
__device__ __forceinline__ void ldsm_x2(uint32_t* r, uint32_t addr) {
    asm volatile("ldmatrix.sync.aligned.m8n8.x2.shared.b16 {%0,%1}, [%2];"
        : "=r"(r[0]), "=r"(r[1]) : "r"(addr));
}
// D(16x8) += A(16x16) * B(16x8) ; fp16 operands, f32 accum
__device__ __forceinline__ void mma16(float* c, const uint32_t* a, const uint32_t* b) {
    asm volatile(
        "mma.sync.aligned.m16n8k16.row.col.f32.f16.f16.f32 "
        "{%0,%1,%2,%3}, {%4,%5,%6,%7}, {%8,%9}, {%0,%1,%2,%3};\n"
        : "+f"(c[0]), "+f"(c[1]), "+f"(c[2]), "+f"(c[3])
        : "r"(a[0]), "r"(a[1]), "r"(a[2]), "r"(a[3]),
          "r"(b[0]), "r"(b[1]));
}

// ---------------- small kernels ----------------
__global__ void init_kernel() {
    int i = threadIdx.x;
    if (i < En) { d_counts[i] = 0; d_cursor[i] = 0; }
}

__global__ void f2h_kernel(const float* __restrict__ s, __half* __restrict__ d, size_t n4) {
    size_t i = (size_t)blockIdx.x * blockDim.x + threadIdx.x;
    if (i >= n4) return;
    float4 v = reinterpret_cast<const float4*>(s)[i];
    __half2 h0 = __floats2half2_rn(v.x, v.y);
    __half2 h1 = __floats2half2_rn(v.z, v.w);
    uint2 pk;
    pk.x = *reinterpret_cast<uint32_t*>(&h0);
    pk.y = *reinterpret_cast<uint32_t*>(&h1);
    reinterpret_cast<uint2*>(d)[i] = pk;
}

__global__ void routing_kernel(const float* __restrict__ x,
                               const float* __restrict__ Wr,
                               float* __restrict__ logits_out) {
    int warp = threadIdx.x >> 5;
    int lane = threadIdx.x & 31;
    int t = blockIdx.x * (blockDim.x >> 5) + warp;
    if (t >= Tn) return;
    const float* xrow = x + (size_t)t * Hn;
    float acc[En];
#pragma unroll
    for (int e = 0; e < En; e++) acc[e] = 0.f;
    for (int k = lane; k < Hn; k += 32) {
        float xv = xrow[k];
#pragma unroll
        for (int e = 0; e < En; e++) acc[e] += xv * Wr[e * Hn + k];
    }
#pragma unroll
    for (int e = 0; e < En; e++) {
#pragma unroll
        for (int o = 16; o > 0; o >>= 1)
            acc[e] += __shfl_xor_sync(0xFFFFFFFFu, acc[e], o);
    }
    if (lane == 0) {
        int b0 = 0; float v0 = acc[0];
#pragma unroll
        for (int e = 1; e < En; e++) if (acc[e] > v0) { v0 = acc[e]; b0 = e; }
        int b1 = -1; float v1 = -1e30f;
#pragma unroll
        for (int e = 0; e < En; e++)
            if (e != b0 && acc[e] > v1) { v1 = acc[e]; b1 = e; }
        float w0 = 1.f / (1.f + expf(v1 - v0));
        float w1 = 1.f - w0;
        d_sel[t * 2 + 0] = b0; d_sel[t * 2 + 1] = b1;
        d_wgt[t * 2 + 0] = w0; d_wgt[t * 2 + 1] = w1;
        atomicAdd(&d_counts[b0], 1);
        atomicAdd(&d_counts[b1], 1);
#pragma unroll
        for (int e = 0; e < En; e++) logits_out[(size_t)t * En + e] = acc[e];
    }
}

__global__ void prefix_kernel() {
    if (threadIdx.x == 0) {
        int s = 0;
        for (int e = 0; e < En; e++) { d_offsets[e] = s; s += d_counts[e]; }
    }
}

__global__ void scatter_kernel() {
    int t = blockIdx.x * blockDim.x + threadIdx.x;
    if (t >= Tn) return;
#pragma unroll
    for (int k = 0; k < 2; k++) {
        int e = d_sel[t * 2 + k];
        int p = atomicAdd(&d_cursor[e], 1);
        int slot = d_offsets[e] + p;
        d_slot_token[slot] = t;
        d_slot_wgt[slot] = d_wgt[t * 2 + k];
    }
}

// ---------------- fp16 mma.sync GEMM: BK=64, 4-stage, 1 sync/chunk ----------
// mainloop byte-identical to round-8 winner; epilogue variants:
//   FUSED   : h = silu(g)*u -> fp16 store
//   COMBINE : atomicAdd(out[token] , slot_weight * val)   (MoE down + combine)
//   else    : plain f32 store
#define TSTR 72                    // halves per smem row
#define TILEB (128 * TSTR * 2)     // 18432 B per tile
#define NSTAGE 4

template <bool FUSED, bool GATHER, bool EXPERT, bool COMBINE>
__global__ void __launch_bounds__(256, 1)
mma_gemm(const __half* __restrict__ A, const __half* __restrict__ W0,
         const __half* __restrict__ W1, void* __restrict__ Cv, int K, int ldC) {
    int rowBase = 0, segRows = Tn;
    const __half* W0p = W0;
    const __half* W1p = W1;
    if (EXPERT) {
        int e = blockIdx.z;
        rowBase = d_offsets[e];
        segRows = d_counts[e];
        size_t ws = (size_t)ldC * K;
        W0p = W0 + (size_t)e * ws;
        if (FUSED) W1p = W1 + (size_t)e * ws;
    }
    int byRow = blockIdx.y * 128;
    if (byRow >= segRows) return;
    int bx = blockIdx.x * 128;

    extern __shared__ char sm[];
    uint32_t sA = smem_u32(sm);
    const int NOP = FUSED ? 3 : 2;
    const uint32_t STAGEB = (uint32_t)(NOP * TILEB);

    int tid = threadIdx.x;
    int lane = tid & 31, wid = tid >> 5;
    int gid = lane >> 2, tig = lane & 3;
    int wm = wid & 1, wn = wid >> 1;

    int q_ = tid & 7;
    int row0 = tid >> 3;
    uint32_t dstB[4];
    const __half* aP[4];
    const __half* w0P[4];
    const __half* w1P[4];
#pragma unroll
    for (int it = 0; it < 4; it++) {
        int row = row0 + it * 32;
        dstB[it] = (uint32_t)(row * TSTR * 2 + q_ * 16);
        int lrow = byRow + row;
        int lcl = lrow < segRows ? lrow : (segRows - 1);
        int arow = GATHER ? d_slot_token[rowBase + lcl] : (rowBase + lcl);
        aP[it]  = A   + (size_t)arow * K + q_ * 8;
        w0P[it] = W0p + (size_t)(bx + row) * K + q_ * 8;
        if (FUSED) w1P[it] = W1p + (size_t)(bx + row) * K + q_ * 8;
    }

    uint32_t aOff[4];
#pragma unroll
    for (int mi = 0; mi < 4; mi++) {
        int rowA = wm * 64 + mi * 16 + (lane & 15);
        int colA = ((lane >> 4) & 1) * 8;
        aOff[mi] = (uint32_t)((rowA * TSTR + colA) * 2);
    }
    uint32_t bOff[4];
#pragma unroll
    for (int ni = 0; ni < 4; ni++) {
        int rowB = wn * 32 + ni * 8 + (lane & 7);
        int colB = ((lane >> 3) & 1) * 8;
        bOff[ni] = (uint32_t)((rowB * TSTR + colB) * 2);
    }

    float acc0[4][4][4];
    float acc1[4][4][4];
#pragma unroll
    for (int mi = 0; mi < 4; mi++)
#pragma unroll
        for (int ni = 0; ni < 4; ni++)
#pragma unroll
            for (int r = 0; r < 4; r++) { acc0[mi][ni][r] = 0.f; if (FUSED) acc1[mi][ni][r] = 0.f; }

    auto loadStage = [&](int j) {
        uint32_t st = sA + (uint32_t)(j % NSTAGE) * STAGEB;
        size_t koff = (size_t)j * 64;
#pragma unroll
        for (int it = 0; it < 4; it++)
            cpasync16(st + dstB[it], aP[it] + koff);
#pragma unroll
        for (int it = 0; it < 4; it++)
            cpasync16(st + (uint32_t)TILEB + dstB[it], w0P[it] + koff);
        if (FUSED) {
#pragma unroll
            for (int it = 0; it < 4; it++)
                cpasync16(st + (uint32_t)(2 * TILEB) + dstB[it], w1P[it] + koff);
        }
        cpcommit();
    };

    int NKS = K / 64;
    loadStage(0);
    loadStage(1);
    loadStage(2);

    for (int i = 0; i < NKS; i++) {
        int rem = NKS - 1 - i;
        cpwait(rem > 2 ? 2 : rem);
        __syncthreads();

        uint32_t stA = sA + (uint32_t)(i % NSTAGE) * STAGEB;
        uint32_t stB0 = stA + (uint32_t)TILEB;
        uint32_t stB1 = stA + (uint32_t)(2 * TILEB);

#pragma unroll
        for (int kk = 0; kk < 4; kk++) {
            uint32_t ko = (uint32_t)(kk * 32);
            uint32_t a[4][4];
#pragma unroll
            for (int mi = 0; mi < 4; mi++)
                ldsm_x4(a[mi], stA + aOff[mi] + ko);
            uint32_t b[4][2];
#pragma unroll
            for (int ni = 0; ni < 4; ni++)
                ldsm_x2(b[ni], stB0 + bOff[ni] + ko);
#pragma unroll
            for (int mi = 0; mi < 4; mi++)
#pragma unroll
                for (int ni = 0; ni < 4; ni++)
                    mma16(acc0[mi][ni], a[mi], b[ni]);
            if (FUSED) {
#pragma unroll
                for (int ni = 0; ni < 4; ni++)
                    ldsm_x2(b[ni], stB1 + bOff[ni] + ko);
#pragma unroll
                for (int mi = 0; mi < 4; mi++)
#pragma unroll
                    for (int ni = 0; ni < 4; ni++)
                        mma16(acc1[mi][ni], a[mi], b[ni]);
            }
        }
        if (i + 3 < NKS) loadStage(i + 3);
    }

    // ---- epilogue ----
#pragma unroll
    for (int mi = 0; mi < 4; mi++) {
        int lr0 = byRow + wm * 64 + mi * 16 + gid;
#pragma unroll
        for (int half = 0; half < 2; half++) {
            int lr = lr0 + half * 8;
            if (lr >= segRows) continue;
            if (FUSED) {
                __half* Ch = (__half*)Cv;
                size_t cbase = (size_t)(rowBase + lr) * ldC + bx + wn * 32 + 2 * tig;
#pragma unroll
                for (int ni = 0; ni < 4; ni++) {
                    float g0 = acc0[mi][ni][half * 2 + 0];
                    float g1 = acc0[mi][ni][half * 2 + 1];
                    float u0 = acc1[mi][ni][half * 2 + 0];
                    float u1 = acc1[mi][ni][half * 2 + 1];
                    float h0 = g0 / (1.f + expf(-g0)) * u0;
                    float h1 = g1 / (1.f + expf(-g1)) * u1;
                    *reinterpret_cast<__half2*>(Ch + cbase + ni * 8) =
                        __floats2half2_rn(h0, h1);
                }
            } else if (COMBINE) {
                // MoE down + combine: out[token] += w_slot * val
                float* Cf = (float*)Cv;
                int slot = rowBase + lr;
                int token = d_slot_token[slot];
                float w = d_slot_wgt[slot];
                float* op = Cf + (size_t)token * ldC + bx + wn * 32 + 2 * tig;
#pragma unroll
                for (int ni = 0; ni < 4; ni++) {
                    atomicAdd(op + ni * 8,     w * acc0[mi][ni][half * 2 + 0]);
                    atomicAdd(op + ni * 8 + 1, w * acc0[mi][ni][half * 2 + 1]);
                }
            } else {
                float* Cf = (float*)Cv;
                size_t cbase = (size_t)(rowBase + lr) * ldC + bx + wn * 32 + 2 * tig;
#pragma unroll
                for (int ni = 0; ni < 4; ni++)
                    *reinterpret_cast<float2*>(Cf + cbase + ni * 8) =
                        make_float2(acc0[mi][ni][half * 2 + 0], acc0[mi][ni][half * 2 + 1]);
            }
        }
    }
}

// ---------------- launch ----------------
extern "C" void kernel_launch(void* const* d_in, const int* in_sizes, int n_in,
                              void* d_out, int out_size) {
    const float* x    = (const float*)d_in[0];
    const float* Wg_s = (const float*)d_in[1];
    const float* Wu_s = (const float*)d_in[2];
    const float* Wd_s = (const float*)d_in[3];
    const float* Wg   = (const float*)d_in[4];
    const float* Wu   = (const float*)d_in[5];
    const float* Wd   = (const float*)d_in[6];
    const float* Wr   = (const float*)d_in[7];
    float* out = (float*)d_out;

    __half *xh, *gsh, *ush, *dsh, *gh, *uh, *dh, *hp, *h2p;
    float *dlog;
    cudaGetSymbolAddress((void**)&xh,  xh_buf);
    cudaGetSymbolAddress((void**)&gsh, wgs_h);
    cudaGetSymbolAddress((void**)&ush, wus_h);
    cudaGetSymbolAddress((void**)&dsh, wds_h);
    cudaGetSymbolAddress((void**)&gh,  wg_h);
    cudaGetSymbolAddress((void**)&uh,  wu_h);
    cudaGetSymbolAddress((void**)&dh,  wd_h);
    cudaGetSymbolAddress((void**)&hp,  h_buf);
    cudaGetSymbolAddress((void**)&h2p, h2_buf);
    cudaGetSymbolAddress((void**)&dlog, dummy_logits);

    bool has_logits = (out_size >= Tn * Hn + Tn * En);
    float* logits = has_logits ? (out + (size_t)Tn * Hn) : dlog;

    const int SMF = NSTAGE * 3 * TILEB;   // 221184 B
    const int SMD = NSTAGE * 2 * TILEB;   // 147456 B
    cudaFuncSetAttribute(mma_gemm<true,  false, false, false>, cudaFuncAttributeMaxDynamicSharedMemorySize, SMF);
    cudaFuncSetAttribute(mma_gemm<true,  true,  true,  false>, cudaFuncAttributeMaxDynamicSharedMemorySize, SMF);
    cudaFuncSetAttribute(mma_gemm<false, false, false, false>, cudaFuncAttributeMaxDynamicSharedMemorySize, SMD);
    cudaFuncSetAttribute(mma_gemm<false, false, true,  true >, cudaFuncAttributeMaxDynamicSharedMemorySize, SMD);

    auto convN = [&](const float* s, __half* d, size_t n, cudaStream_t st) {
        size_t n4 = n / 4;
        f2h_kernel<<<(unsigned)((n4 + 255) / 256), 256, 0, st>>>(s, d, n4);
    };

    // ================= 3-stream schedule =================
    // main: xh conv -> shared convs -> shared fused -> shared down (writes out)
    // s3:   routing chain -> evRoute ; then dh conv -> evDh
    // s2:   gh,uh convs ; wait(evXh, evRoute) -> MoE fused ;
    //       wait(evDh, evOut) -> MoE down (epilogue = combine via atomicAdd)
    cudaEventRecord(g_ss.evFork, 0);
    cudaStreamWaitEvent(g_ss.s2, g_ss.evFork, 0);
    cudaStreamWaitEvent(g_ss.s3, g_ss.evFork, 0);

    // main: x -> fp16 (both GEMM chains gate on this, not on routing)
    convN(x, xh, (size_t)Tn * Hn, 0);
    cudaEventRecord(g_ss.evXh, 0);

    // s3: routing chain (pure f32, independent of xh), then MoE down-weights
    init_kernel<<<1, 32, 0, g_ss.s3>>>();
    routing_kernel<<<Tn / 4, 128, 0, g_ss.s3>>>(x, Wr, logits);
    prefix_kernel<<<1, 32, 0, g_ss.s3>>>();
    scatter_kernel<<<Tn / 256, 256, 0, g_ss.s3>>>();
    cudaEventRecord(g_ss.evRoute, g_ss.s3);
    convN(Wd, dh, (size_t)En * Hn * In, g_ss.s3);
    cudaEventRecord(g_ss.evDh, g_ss.s3);

    // s2: MoE gate/up weight convs
    convN(Wg, gh, (size_t)En * In * Hn, g_ss.s2);
    convN(Wu, uh, (size_t)En * In * Hn, g_ss.s2);

    // main: shared weight convs + shared GEMM chain
    convN(Wg_s, gsh, (size_t)In * Hn, 0);
    convN(Wu_s, ush, (size_t)In * Hn, 0);
    convN(Wd_s, dsh, (size_t)Hn * In, 0);
    mma_gemm<true, false, false, false><<<dim3(In / 128, Tn / 128), 256, SMF>>>(
        xh, gsh, ush, hp, Hn, In);
    mma_gemm<false, false, false, false><<<dim3(Hn / 128, Tn / 128), 256, SMD>>>(
        hp, dsh, nullptr, out, In, Hn);
    cudaEventRecord(g_ss.evOut, 0);

    // s2: MoE GEMM chain
    cudaStreamWaitEvent(g_ss.s2, g_ss.evXh, 0);
    cudaStreamWaitEvent(g_ss.s2, g_ss.evRoute, 0);
    mma_gemm<true, true, true, false><<<dim3(In / 128, Tn / 128, En), 256, SMF, g_ss.s2>>>(
        xh, gh, uh, h2p, Hn, In);
    cudaStreamWaitEvent(g_ss.s2, g_ss.evDh, 0);
    cudaStreamWaitEvent(g_ss.s2, g_ss.evOut, 0);
    mma_gemm<false, false, true, true><<<dim3(Hn / 128, Tn / 128, En), 256, SMD, g_ss.s2>>>(
        h2p, dh, nullptr, out, In, Hn);
    cudaEventRecord(g_ss.evDone, g_ss.s2);

    // join
    cudaStreamWaitEvent(0, g_ss.evDone, 0);
}

// round 13
// speedup vs baseline: 1.0256x; 1.0256x over previous
#include <cuda_runtime.h>
#include <cuda_fp16.h>
#include <cstdint>
#include <math.h>

#define Tn 4096
#define Hn 1024
#define In 2816
#define En 7

// ---------------- static scratch ----------------
__device__ __half xh_buf[(size_t)Tn * Hn];
__device__ __half wgs_h[(size_t)In * Hn];
__device__ __half wus_h[(size_t)In * Hn];
__device__ __half wds_h[(size_t)Hn * In];
__device__ __half wg_h[(size_t)En * In * Hn];
__device__ __half wu_h[(size_t)En * In * Hn];
__device__ __half wd_h[(size_t)En * Hn * In];
__device__ __half h_buf[(size_t)Tn * In];
__device__ __half h2_buf[(size_t)2 * Tn * In];
__device__ float  dummy_logits[(size_t)Tn * En];

__device__ int   d_counts[En];
__device__ int   d_offsets[En];
__device__ int   d_cursor[En];
__device__ int   d_sel[Tn * 2];
__device__ float d_wgt[Tn * 2];
__device__ int   d_slot_token[2 * Tn];
__device__ float d_slot_wgt[2 * Tn];

// ---------------- streams/events (created at load time; not device-memory
// allocations) ----------------
struct SideStream {
    cudaStream_t s2, s3;
    cudaEvent_t  evFork, evXh, evRoute, evDh, evZero, evDone;
    SideStream() {
        cudaStreamCreateWithFlags(&s2, cudaStreamNonBlocking);
        cudaStreamCreateWithFlags(&s3, cudaStreamNonBlocking);
        cudaEventCreateWithFlags(&evFork,  cudaEventDisableTiming);
        cudaEventCreateWithFlags(&evXh,    cudaEventDisableTiming);
        cudaEventCreateWithFlags(&evRoute, cudaEventDisableTiming);
        cudaEventCreateWithFlags(&evDh,    cudaEventDisableTiming);
        cudaEventCreateWithFlags(&evZero,  cudaEventDisableTiming);
        cudaEventCreateWithFlags(&evDone,  cudaEventDisableTiming);
    }
};
static SideStream g_ss;

// ---------------- PTX helpers (portable, sm_80+) ----------------
__device__ __forceinline__ uint32_t smem_u32(const void* p) {
    uint32_t a;
    asm("{ .reg .u64 t; cvta.to.shared.u64 t, %1; cvt.u32.u64 %0, t; }" : "=r"(a) : "l"(p));
    return a;
}
__device__ __forceinline__ void cpasync16(uint32_t dst, const void* src) {
    asm volatile("cp.async.cg.shared.global [%0], [%1], 16;" :: "r"(dst), "l"(src) : "memory");
}
__device__ __forceinline__ void cpcommit() {
    asm volatile("cp.async.commit_group;" ::: "memory");
}
__device__ __forceinline__ void cpwait(int n) {
    if (n <= 0)      asm volatile("cp.async.wait_group 0;" ::: "memory");
    else if (n == 1) asm volatile("cp.async.wait_group 1;" ::: "memory");
    else             asm volatile("cp.async.wait_group 2;" ::: "memory");
}
__device__ __forceinline__ void ldsm_x4(uint32_t* r, uint32_t addr) {
    asm volatile("ldmatrix.sync.aligned.m8n8.x4.shared.b16 {%0,%1,%2,%3}, [%4];"
        : "=r"(r[0]), "=r"(r[1]), "=r"(r[2]), "=r"(r[3]) : "r"(addr));
}
__device__ __forceinline__ void ldsm_x2(uint32_t* r, uint32_t addr) {
    asm volatile("ldmatrix.sync.aligned.m8n8.x2.shared.b16 {%0,%1}, [%2];"
        : "=r"(r[0]), "=r"(r[1]) : "r"(addr));
}
// D(16x8) += A(16x16) * B(16x8) ; fp16 operands, f32 accum
__device__ __forceinline__ void mma16(float* c, const uint32_t* a, const uint32_t* b) {
    asm volatile(
        "mma.sync.aligned.m16n8k16.row.col.f32.f16.f16.f32 "
        "{%0,%1,%2,%3}, {%4,%5,%6,%7}, {%8,%9}, {%0,%1,%2,%3};\n"
        : "+f"(c[0]), "+f"(c[1]), "+f"(c[2]), "+f"(c[3])
        : "r"(a[0]), "r"(a[1]), "r"(a[2]), "r"(a[3]),
          "r"(b[0]), "r"(b[1]));
}

// ---------------- small kernels ----------------
__global__ void init_kernel() {
    int i = threadIdx.x;
    if (i < En) { d_counts[i] = 0; d_cursor[i] = 0; }
}

__global__ void f2h_kernel(const float* __restrict__ s, __half* __restrict__ d, size_t n4) {
    size_t i = (size_t)blockIdx.x * blockDim.x + threadIdx.x;
    if (i >= n4) return;
    float4 v = reinterpret_cast<const float4*>(s)[i];
    __half2 h0 = __floats2half2_rn(v.x, v.y);
    __half2 h1 = __floats2half2_rn(v.z, v.w);
    uint2 pk;
    pk.x = *reinterpret_cast<uint32_t*>(&h0);
    pk.y = *reinterpret_cast<uint32_t*>(&h1);
    reinterpret_cast<uint2*>(d)[i] = pk;
}

__global__ void routing_kernel(const float* __restrict__ x,
                               const float* __restrict__ Wr,
                               float* __restrict__ logits_out) {
    int warp = threadIdx.x >> 5;
    int lane = threadIdx.x & 31;
    int t = blockIdx.x * (blockDim.x >> 5) + warp;
    if (t >= Tn) return;
    const float* xrow = x + (size_t)t * Hn;
    float acc[En];
#pragma unroll
    for (int e = 0; e < En; e++) acc[e] = 0.f;
    for (int k = lane; k < Hn; k += 32) {
        float xv = xrow[k];
#pragma unroll
        for (int e = 0; e < En; e++) acc[e] += xv * Wr[e * Hn + k];
    }
#pragma unroll
    for (int e = 0; e < En; e++) {
#pragma unroll
        for (int o = 16; o > 0; o >>= 1)
            acc[e] += __shfl_xor_sync(0xFFFFFFFFu, acc[e], o);
    }
    if (lane == 0) {
        int b0 = 0; float v0 = acc[0];
#pragma unroll
        for (int e = 1; e < En; e++) if (acc[e] > v0) { v0 = acc[e]; b0 = e; }
        int b1 = -1; float v1 = -1e30f;
#pragma unroll
        for (int e = 0; e < En; e++)
            if (e != b0 && acc[e] > v1) { v1 = acc[e]; b1 = e; }
        float w0 = 1.f / (1.f + expf(v1 - v0));
        float w1 = 1.f - w0;
        d_sel[t * 2 + 0] = b0; d_sel[t * 2 + 1] = b1;
        d_wgt[t * 2 + 0] = w0; d_wgt[t * 2 + 1] = w1;
        atomicAdd(&d_counts[b0], 1);
        atomicAdd(&d_counts[b1], 1);
#pragma unroll
        for (int e = 0; e < En; e++) logits_out[(size_t)t * En + e] = acc[e];
    }
}

__global__ void prefix_kernel() {
    if (threadIdx.x == 0) {
        int s = 0;
        for (int e = 0; e < En; e++) { d_offsets[e] = s; s += d_counts[e]; }
    }
}

__global__ void scatter_kernel() {
    int t = blockIdx.x * blockDim.x + threadIdx.x;
    if (t >= Tn) return;
#pragma unroll
    for (int k = 0; k < 2; k++) {
        int e = d_sel[t * 2 + k];
        int p = atomicAdd(&d_cursor[e], 1);
        int slot = d_offsets[e] + p;
        d_slot_token[slot] = t;
        d_slot_wgt[slot] = d_wgt[t * 2 + k];
    }
}

// ---------------- fp16 mma.sync GEMM: BK=64, 4-stage, 1 sync/chunk ----------
// mainloop byte-identical to round-8 winner; epilogue variants:
//   FUSED   : h = silu(g)*u -> fp16 store
//   COMBINE : atomicAdd(out[token], w*val). EXPERT -> token/w via slot tables;
//             !EXPERT -> token=row, w=1 (shared expert). Requires out zeroed.
//   else    : plain f32 store
#define TSTR 72                    // halves per smem row
#define TILEB (128 * TSTR * 2)     // 18432 B per tile
#define NSTAGE 4

template <bool FUSED, bool GATHER, bool EXPERT, bool COMBINE>
__global__ void __launch_bounds__(256, 1)
mma_gemm(const __half* __restrict__ A, const __half* __restrict__ W0,
         const __half* __restrict__ W1, void* __restrict__ Cv, int K, int ldC) {
    int rowBase = 0, segRows = Tn;
    const __half* W0p = W0;
    const __half* W1p = W1;
    if (EXPERT) {
        int e = blockIdx.z;
        rowBase = d_offsets[e];
        segRows = d_counts[e];
        size_t ws = (size_t)ldC * K;
        W0p = W0 + (size_t)e * ws;
        if (FUSED) W1p = W1 + (size_t)e * ws;
    }
    int byRow = blockIdx.y * 128;
    if (byRow >= segRows) return;
    int bx = blockIdx.x * 128;

    extern __shared__ char sm[];
    uint32_t sA = smem_u32(sm);
    const int NOP = FUSED ? 3 : 2;
    const uint32_t STAGEB = (uint32_t)(NOP * TILEB);

    int tid = threadIdx.x;
    int lane = tid & 31, wid = tid >> 5;
    int gid = lane >> 2, tig = lane & 3;
    int wm = wid & 1, wn = wid >> 1;

    int q_ = tid & 7;
    int row0 = tid >> 3;
    uint32_t dstB[4];
    const __half* aP[4];
    const __half* w0P[4];
    const __half* w1P[4];
#pragma unroll
    for (int it = 0; it < 4; it++) {
        int row = row0 + it * 32;
        dstB[it] = (uint32_t)(row * TSTR * 2 + q_ * 16);
        int lrow = byRow + row;
        int lcl = lrow < segRows ? lrow : (segRows - 1);
        int arow = GATHER ? d_slot_token[rowBase + lcl] : (rowBase + lcl);
        aP[it]  = A   + (size_t)arow * K + q_ * 8;
        w0P[it] = W0p + (size_t)(bx + row) * K + q_ * 8;
        if (FUSED) w1P[it] = W1p + (size_t)(bx + row) * K + q_ * 8;
    }

    uint32_t aOff[4];
#pragma unroll
    for (int mi = 0; mi < 4; mi++) {
        int rowA = wm * 64 + mi * 16 + (lane & 15);
        int colA = ((lane >> 4) & 1) * 8;
        aOff[mi] = (uint32_t)((rowA * TSTR + colA) * 2);
    }
    uint32_t bOff[4];
#pragma unroll
    for (int ni = 0; ni < 4; ni++) {
        int rowB = wn * 32 + ni * 8 + (lane & 7);
        int colB = ((lane >> 3) & 1) * 8;
        bOff[ni] = (uint32_t)((rowB * TSTR + colB) * 2);
    }

    float acc0[4][4][4];
    float acc1[4][4][4];
#pragma unroll
    for (int mi = 0; mi < 4; mi++)
#pragma unroll
        for (int ni = 0; ni < 4; ni++)
#pragma unroll
            for (int r = 0; r < 4; r++) { acc0[mi][ni][r] = 0.f; if (FUSED) acc1[mi][ni][r] = 0.f; }

    auto loadStage = [&](int j) {
        uint32_t st = sA + (uint32_t)(j % NSTAGE) * STAGEB;
        size_t koff = (size_t)j * 64;
#pragma unroll
        for (int it = 0; it < 4; it++)
            cpasync16(st + dstB[it], aP[it] + koff);
#pragma unroll
        for (int it = 0; it < 4; it++)
            cpasync16(st + (uint32_t)TILEB + dstB[it], w0P[it] + koff);
        if (FUSED) {
#pragma unroll
            for (int it = 0; it < 4; it++)
                cpasync16(st + (uint32_t)(2 * TILEB) + dstB[it], w1P[it] + koff);
        }
        cpcommit();
    };

    int NKS = K / 64;
    loadStage(0);
    loadStage(1);
    loadStage(2);

    for (int i = 0; i < NKS; i++) {
        int rem = NKS - 1 - i;
        cpwait(rem > 2 ? 2 : rem);
        __syncthreads();

        uint32_t stA = sA + (uint32_t)(i % NSTAGE) * STAGEB;
        uint32_t stB0 = stA + (uint32_t)TILEB;
        uint32_t stB1 = stA + (uint32_t)(2 * TILEB);

#pragma unroll
        for (int kk = 0; kk < 4; kk++) {
            uint32_t ko = (uint32_t)(kk * 32);
            uint32_t a[4][4];
#pragma unroll
            for (int mi = 0; mi < 4; mi++)
                ldsm_x4(a[mi], stA + aOff[mi] + ko);
            uint32_t b[4][2];
#pragma unroll
            for (int ni = 0; ni < 4; ni++)
                ldsm_x2(b[ni], stB0 + bOff[ni] + ko);
#pragma unroll
            for (int mi = 0; mi < 4; mi++)
#pragma unroll
                for (int ni = 0; ni < 4; ni++)
                    mma16(acc0[mi][ni], a[mi], b[ni]);
            if (FUSED) {
#pragma unroll
                for (int ni = 0; ni < 4; ni++)
                    ldsm_x2(b[ni], stB1 + bOff[ni] + ko);
#pragma unroll
                for (int mi = 0; mi < 4; mi++)
#pragma unroll
                    for (int ni = 0; ni < 4; ni++)
                        mma16(acc1[mi][ni], a[mi], b[ni]);
            }
        }
        if (i + 3 < NKS) loadStage(i + 3);
    }

    // ---- epilogue ----
#pragma unroll
    for (int mi = 0; mi < 4; mi++) {
        int lr0 = byRow + wm * 64 + mi * 16 + gid;
#pragma unroll
        for (int half = 0; half < 2; half++) {
            int lr = lr0 + half * 8;
            if (lr >= segRows) continue;
            if (FUSED) {
                __half* Ch = (__half*)Cv;
                size_t cbase = (size_t)(rowBase + lr) * ldC + bx + wn * 32 + 2 * tig;
#pragma unroll
                for (int ni = 0; ni < 4; ni++) {
                    float g0 = acc0[mi][ni][half * 2 + 0];
                    float g1 = acc0[mi][ni][half * 2 + 1];
                    float u0 = acc1[mi][ni][half * 2 + 0];
                    float u1 = acc1[mi][ni][half * 2 + 1];
                    float h0 = g0 / (1.f + expf(-g0)) * u0;
                    float h1 = g1 / (1.f + expf(-g1)) * u1;
                    *reinterpret_cast<__half2*>(Ch + cbase + ni * 8) =
                        __floats2half2_rn(h0, h1);
                }
            } else if (COMBINE) {
                // accumulate into zero-initialized out: out[token] += w * val
                float* Cf = (float*)Cv;
                int token;
                float w;
                if (EXPERT) {
                    int slot = rowBase + lr;
                    token = d_slot_token[slot];
                    w = d_slot_wgt[slot];
                } else {
                    token = rowBase + lr;
                    w = 1.0f;
                }
                float* op = Cf + (size_t)token * ldC + bx + wn * 32 + 2 * tig;
#pragma unroll
                for (int ni = 0; ni < 4; ni++) {
                    atomicAdd(op + ni * 8,     w * acc0[mi][ni][half * 2 + 0]);
                    atomicAdd(op + ni * 8 + 1, w * acc0[mi][ni][half * 2 + 1]);
                }
            } else {
                float* Cf = (float*)Cv;
                size_t cbase = (size_t)(rowBase + lr) * ldC + bx + wn * 32 + 2 * tig;
#pragma unroll
                for (int ni = 0; ni < 4; ni++)
                    *reinterpret_cast<float2*>(Cf + cbase + ni * 8) =
                        make_float2(acc0[mi][ni][half * 2 + 0], acc0[mi][ni][half * 2 + 1]);
            }
        }
    }
}

// ---------------- launch ----------------
extern "C" void kernel_launch(void* const* d_in, const int* in_sizes, int n_in,
                              void* d_out, int out_size) {
    const float* x    = (const float*)d_in[0];
    const float* Wg_s = (const float*)d_in[1];
    const float* Wu_s = (const float*)d_in[2];
    const float* Wd_s = (const float*)d_in[3];
    const float* Wg   = (const float*)d_in[4];
    const float* Wu   = (const float*)d_in[5];
    const float* Wd   = (const float*)d_in[6];
    const float* Wr   = (const float*)d_in[7];
    float* out = (float*)d_out;

    __half *xh, *gsh, *ush, *dsh, *gh, *uh, *dh, *hp, *h2p;
    float *dlog;
    cudaGetSymbolAddress((void**)&xh,  xh_buf);
    cudaGetSymbolAddress((void**)&gsh, wgs_h);
    cudaGetSymbolAddress((void**)&ush, wus_h);
    cudaGetSymbolAddress((void**)&dsh, wds_h);
    cudaGetSymbolAddress((void**)&gh,  wg_h);
    cudaGetSymbolAddress((void**)&uh,  wu_h);
    cudaGetSymbolAddress((void**)&dh,  wd_h);
    cudaGetSymbolAddress((void**)&hp,  h_buf);
    cudaGetSymbolAddress((void**)&h2p, h2_buf);
    cudaGetSymbolAddress((void**)&dlog, dummy_logits);

    bool has_logits = (out_size >= Tn * Hn + Tn * En);
    float* logits = has_logits ? (out + (size_t)Tn * Hn) : dlog;

    const int SMF = NSTAGE * 3 * TILEB;   // 221184 B
    const int SMD = NSTAGE * 2 * TILEB;   // 147456 B
    cudaFuncSetAttribute(mma_gemm<true,  false, false, false>, cudaFuncAttributeMaxDynamicSharedMemorySize, SMF);
    cudaFuncSetAttribute(mma_gemm<true,  true,  true,  false>, cudaFuncAttributeMaxDynamicSharedMemorySize, SMF);
    cudaFuncSetAttribute(mma_gemm<false, false, false, true >, cudaFuncAttributeMaxDynamicSharedMemorySize, SMD);
    cudaFuncSetAttribute(mma_gemm<false, false, true,  true >, cudaFuncAttributeMaxDynamicSharedMemorySize, SMD);

    auto convN = [&](const float* s, __half* d, size_t n, cudaStream_t st) {
        size_t n4 = n / 4;
        f2h_kernel<<<(unsigned)((n4 + 255) / 256), 256, 0, st>>>(s, d, n4);
    };

    // ================= 3-stream schedule (no down-down ordering) ============
    // main: zero(out) -> xh conv -> shared convs -> shared fused ->
    //       shared down (atomic accumulate into out)
    // s3:   routing chain -> evRoute ; dh conv -> evDh
    // s2:   gh,uh convs ; wait(evXh,evRoute) -> MoE fused ;
    //       wait(evDh,evZero) -> MoE down (atomic accumulate into out)
    // Both down GEMMs accumulate concurrently: addition commutes, no evOut.
    cudaEventRecord(g_ss.evFork, 0);
    cudaStreamWaitEvent(g_ss.s2, g_ss.evFork, 0);
    cudaStreamWaitEvent(g_ss.s3, g_ss.evFork, 0);

    // main: zero the output accumulator (first Tn*Hn floats only), then xh
    cudaMemsetAsync(out, 0, (size_t)Tn * Hn * sizeof(float), 0);
    cudaEventRecord(g_ss.evZero, 0);
    convN(x, xh, (size_t)Tn * Hn, 0);
    cudaEventRecord(g_ss.evXh, 0);

    // s3: routing chain (pure f32, independent of xh), then MoE down-weights
    init_kernel<<<1, 32, 0, g_ss.s3>>>();
    routing_kernel<<<Tn / 4, 128, 0, g_ss.s3>>>(x, Wr, logits);
    prefix_kernel<<<1, 32, 0, g_ss.s3>>>();
    scatter_kernel<<<Tn / 256, 256, 0, g_ss.s3>>>();
    cudaEventRecord(g_ss.evRoute, g_ss.s3);
    convN(Wd, dh, (size_t)En * Hn * In, g_ss.s3);
    cudaEventRecord(g_ss.evDh, g_ss.s3);

    // s2: MoE gate/up weight convs
    convN(Wg, gh, (size_t)En * In * Hn, g_ss.s2);
    convN(Wu, uh, (size_t)En * In * Hn, g_ss.s2);

    // main: shared weight convs + shared GEMM chain
    convN(Wg_s, gsh, (size_t)In * Hn, 0);
    convN(Wu_s, ush, (size_t)In * Hn, 0);
    convN(Wd_s, dsh, (size_t)Hn * In, 0);
    mma_gemm<true, false, false, false><<<dim3(In / 128, Tn / 128), 256, SMF>>>(
        xh, gsh, ush, hp, Hn, In);
    mma_gemm<false, false, false, true><<<dim3(Hn / 128, Tn / 128), 256, SMD>>>(
        hp, dsh, nullptr, out, In, Hn);

    // s2: MoE GEMM chain (concurrent with shared chain; atomics commute)
    cudaStreamWaitEvent(g_ss.s2, g_ss.evXh, 0);
    cudaStreamWaitEvent(g_ss.s2, g_ss.evRoute, 0);
    mma_gemm<true, true, true, false><<<dim3(In / 128, Tn / 128, En), 256, SMF, g_ss.s2>>>(
        xh, gh, uh, h2p, Hn, In);
    cudaStreamWaitEvent(g_ss.s2, g_ss.evDh, 0);
    cudaStreamWaitEvent(g_ss.s2, g_ss.evZero, 0);
    mma_gemm<false, false, true, true><<<dim3(Hn / 128, Tn / 128, En), 256, SMD, g_ss.s2>>>(
        h2p, dh, nullptr, out, In, Hn);
    cudaEventRecord(g_ss.evDone, g_ss.s2);

    // join
    cudaStreamWaitEvent(0, g_ss.evDone, 0);
}